// round 12
// baseline (speedup 1.0000x reference)
#include <cuda_runtime.h>
#include <cuda_fp16.h>
#include <cstdint>

#define N_POSN 8192
#define NB     4
#define NG     512
#define NJ     2048   /* NB*NG */
#define NREP   8
#define EPSF   1e-6f

// ---------------- device scratch (allocation-free) ----------------
__device__ __half g_Dg16[(long long)N_POSN * NJ]; // 32MB compact gathered columns, [n][j], fp16
__device__ float  g_rowmin[NB * N_POSN];          // min_g D[n,g] per batch, [b][n] (fp32, exact)
__device__ float  g_S8[NREP][NJ];                 // replicated sum_n 1/(w+eps)
__device__ float  g_t1[NB];
__device__ float  g_ne[NB];
__device__ int    g_maxbits;                      // atomicMax, idempotent across replays (dis>=0)
__device__ float  g_pmin;
__device__ float  g_pmax;

// ---------------- kernel 1: stream dis_matrix once (UNCHANGED from R11) ----------------
// 256 thr, 1024 CTAs x 8 rows. Per row: issue next row's 8x LDG.128 into regs
// FIRST (DRAM latency hides behind the gather), gather pairs from smem ->
// half2 compact store, rowmin via warp+smem reduce, barrier, regs->smem, barrier.
__global__ void __launch_bounds__(256) k_gather(const float* __restrict__ dis,
                                                const int* __restrict__ gt,
                                                const float* __restrict__ pm) {
    __shared__ float srow[N_POSN];           // 32KB
    __shared__ int   sminw[2][NB][8];        // per-warp per-batch min bits (double-buffered)
    __shared__ int   spmin[8], spmax[8];
    const int tid = threadIdx.x;
    const int wid = tid >> 5;

    // thread owns j = it*512 + 2*tid + {0,1}; batch = it
    int mycol[8];
    #pragma unroll
    for (int it = 0; it < 4; it++) {
        mycol[2 * it]     = gt[it * 512 + 2 * tid];
        mycol[2 * it + 1] = gt[it * 512 + 2 * tid + 1];
    }

    const int n0 = blockIdx.x * 8;           // 1024 CTAs x 8 rows
    float lmax = 0.0f;

    // prologue: row n0 -> srow
    {
        const float4* src = reinterpret_cast<const float4*>(dis + (long long)n0 * N_POSN);
        float4* dst = reinterpret_cast<float4*>(srow);
        #pragma unroll
        for (int i = 0; i < 8; i++) {
            float4 v = __ldcs(src + i * 256 + tid);
            lmax = fmaxf(lmax, fmaxf(fmaxf(v.x, v.y), fmaxf(v.z, v.w)));
            dst[i * 256 + tid] = v;
        }
    }
    __syncthreads();

    #pragma unroll
    for (int r = 0; r < 8; r++) {
        const int n = n0 + r;

        // 1) issue next row's loads NOW — they land while we gather below
        float4 v[8];
        if (r < 7) {
            const float4* src = reinterpret_cast<const float4*>(dis + (long long)(n + 1) * N_POSN);
            #pragma unroll
            for (int i = 0; i < 8; i++) v[i] = __ldcs(src + i * 256 + tid);
        }

        // 2) gather pairs from srow -> half2 compact store (coalesced)
        __half2* out2 = reinterpret_cast<__half2*>(g_Dg16 + (long long)n * NJ);
        float lmin[4];
        #pragma unroll
        for (int it = 0; it < 4; it++) {
            float a = srow[mycol[2 * it]];
            float b = srow[mycol[2 * it + 1]];
            out2[it * 256 + tid] = __floats2half2_rn(a, b);
            lmin[it] = fminf(a, b);
        }

        // 3) per-batch rowmin: warp reduce -> sminw[r&1]
        #pragma unroll
        for (int b = 0; b < NB; b++) {
            float m = lmin[b];
            #pragma unroll
            for (int o = 16; o; o >>= 1)
                m = fminf(m, __shfl_xor_sync(0xFFFFFFFFu, m, o));
            if ((tid & 31) == 0) sminw[r & 1][b][wid] = __float_as_int(m);
        }
        __syncthreads();   // srow reads + sminw writes done

        // 4a) threads 0-3: finish rowmin reduce, plain store (fp32 exact)
        if (tid < NB) {
            int mb = sminw[r & 1][tid][0];
            #pragma unroll
            for (int w = 1; w < 8; w++) mb = min(mb, sminw[r & 1][tid][w]);
            g_rowmin[tid * N_POSN + n] = __int_as_float(mb);
        }
        // 4b) store prefetched row into srow + fold into max
        if (r < 7) {
            float4* dst = reinterpret_cast<float4*>(srow);
            #pragma unroll
            for (int i = 0; i < 8; i++) {
                float4 w = v[i];
                lmax = fmaxf(lmax, fmaxf(fmaxf(w.x, w.y), fmaxf(w.z, w.w)));
                dst[i * 256 + tid] = w;
            }
            __syncthreads();   // srow visible; sminw[r&1] safe for reuse at r+2
        }
    }

    #pragma unroll
    for (int o = 16; o; o >>= 1)
        lmax = fmaxf(lmax, __shfl_xor_sync(0xFFFFFFFFu, lmax, o));
    if ((tid & 31) == 0) atomicMax(&g_maxbits, __float_as_int(lmax));

    // ---- CTA 0 extra duties (ordered before k_main by the kernel boundary) ----
    if (blockIdx.x == 0) {
        float* s8 = &g_S8[0][0];
        for (int i = tid; i < NREP * NJ; i += 256) s8[i] = 0.0f;
        if (tid < NB) { g_t1[tid] = 0.0f; g_ne[tid] = 0.0f; }

        float mn = __int_as_float(0x7F7FFFFF);
        float mx = -__int_as_float(0x7F7FFFFF);
        const float4* pm4 = reinterpret_cast<const float4*>(pm);
        for (int i = tid; i < (NB * N_POSN) / 4; i += 256) {
            float4 v = pm4[i];
            mn = fminf(mn, fminf(fminf(v.x, v.y), fminf(v.z, v.w)));
            mx = fmaxf(mx, fmaxf(fmaxf(v.x, v.y), fmaxf(v.z, v.w)));
        }
        #pragma unroll
        for (int o = 16; o; o >>= 1) {
            mn = fminf(mn, __shfl_xor_sync(0xFFFFFFFFu, mn, o));
            mx = fmaxf(mx, __shfl_xor_sync(0xFFFFFFFFu, mx, o));
        }
        if ((tid & 31) == 0) { spmin[wid] = __float_as_int(mn); spmax[wid] = __float_as_int(mx); }
        __syncthreads();
        if (tid == 0) {
            int a = spmin[0], b = spmax[0];
            #pragma unroll
            for (int w = 1; w < 8; w++) { a = min(a, spmin[w]); b = max(b, spmax[w]); }
            g_pmin = __int_as_float(a);
            g_pmax = __int_as_float(b);
        }
    }
}

// ---------------- kernel 2: main reduction over compact fp16 Dg ----------------
// 256 CTAs x 256 thr x 32 rows. Thread owns j0 = 8*tid (one LDG.128 = 8 halves
// per row); 4 chunks of 8-deep load batching; 8 atomics/thread at the end
// (524K lane-ops over 8 replicas -> ~32 serialized ops per address).
#define B_ROWS 32
__global__ void __launch_bounds__(256) k_main(const float* __restrict__ pm) {
    const float maxd = __int_as_float(g_maxbits);
    const float pmin = g_pmin;
    const float invr = 1.0f / (g_pmax - pmin);
    const float c0   = maxd + EPSF;

    const int tid = threadIdx.x;
    const int j0  = 8 * tid;                  // 8 consecutive j, all one batch
    const int k   = tid >> 6;                 // batch (warp-uniform)
    const int n0  = blockIdx.x * B_ROWS;      // 256 CTAs

    float acc[8];
    #pragma unroll
    for (int q = 0; q < 8; q++) acc[q] = 0.0f;

    const float* pmk = pm + k * N_POSN;

    #pragma unroll
    for (int c = 0; c < B_ROWS / 8; c++) {
        uint4 d[8];
        float pv[8];
        #pragma unroll
        for (int i = 0; i < 8; i++)
            d[i] = *reinterpret_cast<const uint4*>(g_Dg16 + (long long)(n0 + c * 8 + i) * NJ + j0);
        #pragma unroll
        for (int i = 0; i < 8; i++)
            pv[i] = __ldg(pmk + n0 + c * 8 + i);
        #pragma unroll
        for (int i = 0; i < 8; i++) {
            float p    = fminf(fmaxf((pv[i] - pmin) * invr, 0.0f), 1.0f);
            float base = fmaf(-p, maxd, c0);               // (1-p)*maxd + eps
            const __half2* hp = reinterpret_cast<const __half2*>(&d[i]);
            #pragma unroll
            for (int q = 0; q < 4; q++) {
                float2 f = __half22float2(hp[q]);
                acc[2 * q]     += __fdividef(1.0f, fmaf(p, f.x, base));
                acc[2 * q + 1] += __fdividef(1.0f, fmaf(p, f.y, base));
            }
        }
    }

    float* Srep = g_S8[blockIdx.x & (NREP - 1)];
    #pragma unroll
    for (int q = 0; q < 8; q++)
        atomicAdd(&Srep[j0 + q], acc[q]);

    // term1: 128 threads, one warp per batch, 32 rows each; full-warp reduce.
    if (tid < 128) {
        const int b = tid >> 5;
        const int n = n0 + (tid & 31);
        float pmv = __ldg(pm + b * N_POSN + n);
        float p   = fminf(fmaxf((pmv - pmin) * invr, 0.0f), 1.0f);
        float rm  = g_rowmin[b * N_POSN + n];
        float t1  = p * rm;
        float ne  = p;
        #pragma unroll
        for (int o = 16; o; o >>= 1) {
            t1 += __shfl_xor_sync(0xFFFFFFFFu, t1, o);
            ne += __shfl_xor_sync(0xFFFFFFFFu, ne, o);
        }
        if ((tid & 31) == 0) {
            atomicAdd(&g_t1[b], t1);
            atomicAdd(&g_ne[b], ne);
        }
    }
}

// ---------------- kernel 3: finalize scalar ----------------
__global__ void __launch_bounds__(512) k_final(float* __restrict__ out) {
    __shared__ float ssum[512];
    const int tid = threadIdx.x;
    float s = 0.0f;
    #pragma unroll
    for (int m = 0; m < NJ / 512; m++) {
        int j = tid + m * 512;
        float S = 0.0f;
        #pragma unroll
        for (int rp = 0; rp < NREP; rp++) S += g_S8[rp][j];
        s += (float)N_POSN / S;
    }
    ssum[tid] = s;
    __syncthreads();
    for (int o = 256; o; o >>= 1) {
        if (tid < o) ssum[tid] += ssum[tid + o];
        __syncthreads();
    }
    if (tid == 0) {
        float term2 = ssum[0] / (float)(NB * NG);
        float term1 = 0.0f;
        #pragma unroll
        for (int b = 0; b < NB; b++)
            term1 += g_t1[b] / (g_ne[b] + EPSF);
        term1 *= (1.0f / NB);
        out[0] = term1 + term2;
    }
}

// ---------------- launch ----------------
extern "C" void kernel_launch(void* const* d_in, const int* in_sizes, int n_in,
                              void* d_out, int out_size) {
    (void)in_sizes; (void)n_in; (void)out_size;
    const float* prob_map = (const float*)d_in[0];   // (4, 8192) f32
    const int*   gt       = (const int*)d_in[1];     // (4, 512)  i32
    const float* dis      = (const float*)d_in[2];   // (8192, 8192) f32
    float* out = (float*)d_out;

    k_gather<<<1024, 256>>>(dis, gt, prob_map);
    k_main<<<N_POSN / B_ROWS, 256>>>(prob_map);
    k_final<<<1, 512>>>(out);
}

// round 14
// speedup vs baseline: 1.0683x; 1.0683x over previous
#include <cuda_runtime.h>
#include <cuda_fp16.h>
#include <cstdint>

#define N_POSN 8192
#define NB     4
#define NG     512
#define NJ     2048   /* NB*NG */
#define NREP   8
#define EPSF   1e-6f

// ---------------- device scratch (allocation-free) ----------------
__device__ __half g_Dg16[(long long)N_POSN * NJ]; // 32MB compact gathered columns, [n][j], fp16
__device__ float  g_rowmin[NB * N_POSN];          // min_g D[n,g] per batch, [b][n] (fp32, exact)
__device__ float  g_S8[NREP][NJ];                 // replicated sum_n 1/(w+eps)
__device__ float  g_t1[NB];
__device__ float  g_ne[NB];
__device__ int    g_maxbits;                      // atomicMax, idempotent across replays (dis>=0)
__device__ float  g_pmin;
__device__ float  g_pmax;

// ---------------- kernel 1: stream dis_matrix once (UNCHANGED — proven) ----------------
// 256 thr, 1024 CTAs x 8 rows. Per row: issue next row's 8x LDG.128 into regs
// FIRST (DRAM latency hides behind the gather), gather pairs from smem ->
// half2 compact store, rowmin via warp+smem reduce, barrier, regs->smem, barrier.
__global__ void __launch_bounds__(256) k_gather(const float* __restrict__ dis,
                                                const int* __restrict__ gt,
                                                const float* __restrict__ pm) {
    __shared__ float srow[N_POSN];           // 32KB
    __shared__ int   sminw[2][NB][8];        // per-warp per-batch min bits (double-buffered)
    __shared__ int   spmin[8], spmax[8];
    const int tid = threadIdx.x;
    const int wid = tid >> 5;

    // thread owns j = it*512 + 2*tid + {0,1}; batch = it
    int mycol[8];
    #pragma unroll
    for (int it = 0; it < 4; it++) {
        mycol[2 * it]     = gt[it * 512 + 2 * tid];
        mycol[2 * it + 1] = gt[it * 512 + 2 * tid + 1];
    }

    const int n0 = blockIdx.x * 8;           // 1024 CTAs x 8 rows
    float lmax = 0.0f;

    // prologue: row n0 -> srow
    {
        const float4* src = reinterpret_cast<const float4*>(dis + (long long)n0 * N_POSN);
        float4* dst = reinterpret_cast<float4*>(srow);
        #pragma unroll
        for (int i = 0; i < 8; i++) {
            float4 v = __ldcs(src + i * 256 + tid);
            lmax = fmaxf(lmax, fmaxf(fmaxf(v.x, v.y), fmaxf(v.z, v.w)));
            dst[i * 256 + tid] = v;
        }
    }
    __syncthreads();

    #pragma unroll
    for (int r = 0; r < 8; r++) {
        const int n = n0 + r;

        // 1) issue next row's loads NOW — they land while we gather below
        float4 v[8];
        if (r < 7) {
            const float4* src = reinterpret_cast<const float4*>(dis + (long long)(n + 1) * N_POSN);
            #pragma unroll
            for (int i = 0; i < 8; i++) v[i] = __ldcs(src + i * 256 + tid);
        }

        // 2) gather pairs from srow -> half2 compact store (coalesced)
        __half2* out2 = reinterpret_cast<__half2*>(g_Dg16 + (long long)n * NJ);
        float lmin[4];
        #pragma unroll
        for (int it = 0; it < 4; it++) {
            float a = srow[mycol[2 * it]];
            float b = srow[mycol[2 * it + 1]];
            out2[it * 256 + tid] = __floats2half2_rn(a, b);
            lmin[it] = fminf(a, b);
        }

        // 3) per-batch rowmin: warp reduce -> sminw[r&1]
        #pragma unroll
        for (int b = 0; b < NB; b++) {
            float m = lmin[b];
            #pragma unroll
            for (int o = 16; o; o >>= 1)
                m = fminf(m, __shfl_xor_sync(0xFFFFFFFFu, m, o));
            if ((tid & 31) == 0) sminw[r & 1][b][wid] = __float_as_int(m);
        }
        __syncthreads();   // srow reads + sminw writes done

        // 4a) threads 0-3: finish rowmin reduce, plain store (fp32 exact)
        if (tid < NB) {
            int mb = sminw[r & 1][tid][0];
            #pragma unroll
            for (int w = 1; w < 8; w++) mb = min(mb, sminw[r & 1][tid][w]);
            g_rowmin[tid * N_POSN + n] = __int_as_float(mb);
        }
        // 4b) store prefetched row into srow + fold into max
        if (r < 7) {
            float4* dst = reinterpret_cast<float4*>(srow);
            #pragma unroll
            for (int i = 0; i < 8; i++) {
                float4 w = v[i];
                lmax = fmaxf(lmax, fmaxf(fmaxf(w.x, w.y), fmaxf(w.z, w.w)));
                dst[i * 256 + tid] = w;
            }
            __syncthreads();   // srow visible; sminw[r&1] safe for reuse at r+2
        }
    }

    #pragma unroll
    for (int o = 16; o; o >>= 1)
        lmax = fmaxf(lmax, __shfl_xor_sync(0xFFFFFFFFu, lmax, o));
    if ((tid & 31) == 0) atomicMax(&g_maxbits, __float_as_int(lmax));

    // ---- CTA 0 extra duties (ordered before k_main by the kernel boundary) ----
    if (blockIdx.x == 0) {
        float* s8 = &g_S8[0][0];
        for (int i = tid; i < NREP * NJ; i += 256) s8[i] = 0.0f;
        if (tid < NB) { g_t1[tid] = 0.0f; g_ne[tid] = 0.0f; }

        float mn = __int_as_float(0x7F7FFFFF);
        float mx = -__int_as_float(0x7F7FFFFF);
        const float4* pm4 = reinterpret_cast<const float4*>(pm);
        for (int i = tid; i < (NB * N_POSN) / 4; i += 256) {
            float4 v = pm4[i];
            mn = fminf(mn, fminf(fminf(v.x, v.y), fminf(v.z, v.w)));
            mx = fmaxf(mx, fmaxf(fmaxf(v.x, v.y), fmaxf(v.z, v.w)));
        }
        #pragma unroll
        for (int o = 16; o; o >>= 1) {
            mn = fminf(mn, __shfl_xor_sync(0xFFFFFFFFu, mn, o));
            mx = fmaxf(mx, __shfl_xor_sync(0xFFFFFFFFu, mx, o));
        }
        if ((tid & 31) == 0) { spmin[wid] = __float_as_int(mn); spmax[wid] = __float_as_int(mx); }
        __syncthreads();
        if (tid == 0) {
            int a = spmin[0], b = spmax[0];
            #pragma unroll
            for (int w = 1; w < 8; w++) { a = min(a, spmin[w]); b = max(b, spmax[w]); }
            g_pmin = __int_as_float(a);
            g_pmax = __int_as_float(b);
        }
    }
}

// ---------------- kernel 2: main reduction — R8's proven geometry, fp16 data ----------------
// 512 CTAs x 512 thr x 16 rows. Thread owns 4 consecutive j = 4*tid (one LDG.64
// = 4 halves per row), batch k = tid>>7; explicit 8-deep load batching;
// 4 atomics/thread to 4*tid over 8 replicas (identical atomic pattern to R8).
#define B_ROWS 16
__global__ void __launch_bounds__(512) k_main(const float* __restrict__ pm) {
    const float maxd = __int_as_float(g_maxbits);
    const float pmin = g_pmin;
    const float invr = 1.0f / (g_pmax - pmin);
    const float c0   = maxd + EPSF;

    const int tid = threadIdx.x;
    const int k   = tid >> 7;                 // batch (warp-uniform)
    const int n0  = blockIdx.x * B_ROWS;      // 512 CTAs

    float4 acc = make_float4(0.f, 0.f, 0.f, 0.f);
    const float* pmk = pm + k * N_POSN;

    #pragma unroll
    for (int c = 0; c < B_ROWS / 8; c++) {
        uint2 d[8];
        float pv[8];
        #pragma unroll
        for (int i = 0; i < 8; i++)
            d[i] = *reinterpret_cast<const uint2*>(g_Dg16 + (long long)(n0 + c * 8 + i) * NJ + 4 * tid);
        #pragma unroll
        for (int i = 0; i < 8; i++)
            pv[i] = __ldg(pmk + n0 + c * 8 + i);
        #pragma unroll
        for (int i = 0; i < 8; i++) {
            float p    = fminf(fmaxf((pv[i] - pmin) * invr, 0.0f), 1.0f);
            float base = fmaf(-p, maxd, c0);               // (1-p)*maxd + eps
            float2 f0  = __half22float2(*reinterpret_cast<const __half2*>(&d[i].x));
            float2 f1  = __half22float2(*reinterpret_cast<const __half2*>(&d[i].y));
            acc.x += __fdividef(1.0f, fmaf(p, f0.x, base));
            acc.y += __fdividef(1.0f, fmaf(p, f0.y, base));
            acc.z += __fdividef(1.0f, fmaf(p, f1.x, base));
            acc.w += __fdividef(1.0f, fmaf(p, f1.y, base));
        }
    }

    float* Srep = g_S8[blockIdx.x & (NREP - 1)];
    atomicAdd(&Srep[4 * tid + 0], acc.x);
    atomicAdd(&Srep[4 * tid + 1], acc.y);
    atomicAdd(&Srep[4 * tid + 2], acc.z);
    atomicAdd(&Srep[4 * tid + 3], acc.w);

    // term1: threads 0..63 each handle one (b, row) pair; 16-lane segment reduce.
    if (tid < 64) {
        const int b  = tid >> 4;
        const int n  = n0 + (tid & 15);
        float pmv = __ldg(pm + b * N_POSN + n);
        float p   = fminf(fmaxf((pmv - pmin) * invr, 0.0f), 1.0f);
        float rm  = g_rowmin[b * N_POSN + n];
        float t1  = p * rm;
        float ne  = p;
        #pragma unroll
        for (int o = 8; o; o >>= 1) {
            t1 += __shfl_xor_sync(0xFFFFFFFFu, t1, o);
            ne += __shfl_xor_sync(0xFFFFFFFFu, ne, o);
        }
        if ((tid & 15) == 0) {
            atomicAdd(&g_t1[b], t1);
            atomicAdd(&g_ne[b], ne);
        }
    }
}

// ---------------- kernel 3: finalize scalar ----------------
__global__ void __launch_bounds__(512) k_final(float* __restrict__ out) {
    __shared__ float ssum[512];
    const int tid = threadIdx.x;
    float s = 0.0f;
    #pragma unroll
    for (int m = 0; m < NJ / 512; m++) {
        int j = tid + m * 512;
        float S = 0.0f;
        #pragma unroll
        for (int rp = 0; rp < NREP; rp++) S += g_S8[rp][j];
        s += (float)N_POSN / S;
    }
    ssum[tid] = s;
    __syncthreads();
    for (int o = 256; o; o >>= 1) {
        if (tid < o) ssum[tid] += ssum[tid + o];
        __syncthreads();
    }
    if (tid == 0) {
        float term2 = ssum[0] / (float)(NB * NG);
        float term1 = 0.0f;
        #pragma unroll
        for (int b = 0; b < NB; b++)
            term1 += g_t1[b] / (g_ne[b] + EPSF);
        term1 *= (1.0f / NB);
        out[0] = term1 + term2;
    }
}

// ---------------- launch ----------------
extern "C" void kernel_launch(void* const* d_in, const int* in_sizes, int n_in,
                              void* d_out, int out_size) {
    (void)in_sizes; (void)n_in; (void)out_size;
    const float* prob_map = (const float*)d_in[0];   // (4, 8192) f32
    const int*   gt       = (const int*)d_in[1];     // (4, 512)  i32
    const float* dis      = (const float*)d_in[2];   // (8192, 8192) f32
    float* out = (float*)d_out;

    k_gather<<<1024, 256>>>(dis, gt, prob_map);
    k_main<<<N_POSN / B_ROWS, 512>>>(prob_map);
    k_final<<<1, 512>>>(out);
}

// round 15
// speedup vs baseline: 1.2281x; 1.1496x over previous
#include <cuda_runtime.h>
#include <cuda_fp16.h>
#include <cstdint>

#define N_POSN 8192
#define NB     4
#define NG     512
#define NJ     2048   /* NB*NG */
#define NREP   16
#define EPSF   1e-6f

// ---------------- device scratch (allocation-free) ----------------
// All accumulators start zero (module load) and are re-zeroed by the last CTA
// of k_main after each call -> identical state every graph replay.
__device__ __half   g_Dg16[(long long)N_POSN * NJ]; // 32MB compact gathered columns, [n][j], fp16
__device__ float    g_rowmin[NB * N_POSN];          // min_g D[n,g] per batch, [b][n] (fp32 exact)
__device__ float    g_S[NREP][NJ];                  // replicated sum_n 1/(w+eps)
__device__ float    g_t1[NB];
__device__ float    g_ne[NB];
__device__ int      g_maxbits;                      // max(dis_matrix) bits
__device__ float    g_pmin;
__device__ float    g_pmax;
__device__ unsigned g_done;                         // ticket counter for fused finalize

// ---------------- kernel 1: stream dis_matrix once (proven R14 code) ----------------
// 256 thr, 1024 CTAs x 8 rows. Per row: issue next row's 8x LDG.128 into regs
// FIRST (DRAM latency hides behind the gather), gather pairs from smem ->
// half2 compact store, rowmin via warp+smem reduce, barrier, regs->smem, barrier.
__global__ void __launch_bounds__(256) k_gather(const float* __restrict__ dis,
                                                const int* __restrict__ gt,
                                                const float* __restrict__ pm) {
    __shared__ float srow[N_POSN];           // 32KB
    __shared__ int   sminw[2][NB][8];        // per-warp per-batch min bits (double-buffered)
    __shared__ int   spmin[8], spmax[8];
    const int tid = threadIdx.x;
    const int wid = tid >> 5;

    // thread owns j = it*512 + 2*tid + {0,1}; batch = it
    int mycol[8];
    #pragma unroll
    for (int it = 0; it < 4; it++) {
        mycol[2 * it]     = gt[it * 512 + 2 * tid];
        mycol[2 * it + 1] = gt[it * 512 + 2 * tid + 1];
    }

    const int n0 = blockIdx.x * 8;           // 1024 CTAs x 8 rows
    float lmax = 0.0f;

    // prologue: row n0 -> srow
    {
        const float4* src = reinterpret_cast<const float4*>(dis + (long long)n0 * N_POSN);
        float4* dst = reinterpret_cast<float4*>(srow);
        #pragma unroll
        for (int i = 0; i < 8; i++) {
            float4 v = __ldcs(src + i * 256 + tid);
            lmax = fmaxf(lmax, fmaxf(fmaxf(v.x, v.y), fmaxf(v.z, v.w)));
            dst[i * 256 + tid] = v;
        }
    }
    __syncthreads();

    #pragma unroll
    for (int r = 0; r < 8; r++) {
        const int n = n0 + r;

        // 1) issue next row's loads NOW — they land while we gather below
        float4 v[8];
        if (r < 7) {
            const float4* src = reinterpret_cast<const float4*>(dis + (long long)(n + 1) * N_POSN);
            #pragma unroll
            for (int i = 0; i < 8; i++) v[i] = __ldcs(src + i * 256 + tid);
        }

        // 2) gather pairs from srow -> half2 compact store (coalesced)
        __half2* out2 = reinterpret_cast<__half2*>(g_Dg16 + (long long)n * NJ);
        float lmin[4];
        #pragma unroll
        for (int it = 0; it < 4; it++) {
            float a = srow[mycol[2 * it]];
            float b = srow[mycol[2 * it + 1]];
            out2[it * 256 + tid] = __floats2half2_rn(a, b);
            lmin[it] = fminf(a, b);
        }

        // 3) per-batch rowmin: warp reduce -> sminw[r&1]
        #pragma unroll
        for (int b = 0; b < NB; b++) {
            float m = lmin[b];
            #pragma unroll
            for (int o = 16; o; o >>= 1)
                m = fminf(m, __shfl_xor_sync(0xFFFFFFFFu, m, o));
            if ((tid & 31) == 0) sminw[r & 1][b][wid] = __float_as_int(m);
        }
        __syncthreads();   // srow reads + sminw writes done

        // 4a) threads 0-3: finish rowmin reduce, plain store (fp32 exact)
        if (tid < NB) {
            int mb = sminw[r & 1][tid][0];
            #pragma unroll
            for (int w = 1; w < 8; w++) mb = min(mb, sminw[r & 1][tid][w]);
            g_rowmin[tid * N_POSN + n] = __int_as_float(mb);
        }
        // 4b) store prefetched row into srow + fold into max
        if (r < 7) {
            float4* dst = reinterpret_cast<float4*>(srow);
            #pragma unroll
            for (int i = 0; i < 8; i++) {
                float4 w = v[i];
                lmax = fmaxf(lmax, fmaxf(fmaxf(w.x, w.y), fmaxf(w.z, w.w)));
                dst[i * 256 + tid] = w;
            }
            __syncthreads();   // srow visible; sminw[r&1] safe for reuse at r+2
        }
    }

    #pragma unroll
    for (int o = 16; o; o >>= 1)
        lmax = fmaxf(lmax, __shfl_xor_sync(0xFFFFFFFFu, lmax, o));
    if ((tid & 31) == 0) atomicMax(&g_maxbits, __float_as_int(lmax));

    // ---- CTA 0: prob_map min/max (accumulator zeroing now lives in k_main's finalizer) ----
    if (blockIdx.x == 0) {
        float mn = __int_as_float(0x7F7FFFFF);
        float mx = -__int_as_float(0x7F7FFFFF);
        const float4* pm4 = reinterpret_cast<const float4*>(pm);
        for (int i = tid; i < (NB * N_POSN) / 4; i += 256) {
            float4 v = pm4[i];
            mn = fminf(mn, fminf(fminf(v.x, v.y), fminf(v.z, v.w)));
            mx = fmaxf(mx, fmaxf(fmaxf(v.x, v.y), fmaxf(v.z, v.w)));
        }
        #pragma unroll
        for (int o = 16; o; o >>= 1) {
            mn = fminf(mn, __shfl_xor_sync(0xFFFFFFFFu, mn, o));
            mx = fmaxf(mx, __shfl_xor_sync(0xFFFFFFFFu, mx, o));
        }
        if ((tid & 31) == 0) { spmin[wid] = __float_as_int(mn); spmax[wid] = __float_as_int(mx); }
        __syncthreads();
        if (tid == 0) {
            int a = spmin[0], b = spmax[0];
            #pragma unroll
            for (int w = 1; w < 8; w++) { a = min(a, spmin[w]); b = max(b, spmax[w]); }
            g_pmin = __int_as_float(a);
            g_pmax = __int_as_float(b);
        }
    }
}

// ---------------- kernel 2: main reduction + fused finalize ----------------
// 1024 CTAs x 512 thr x 8 rows. Thread owns 4 consecutive j = 4*tid (LDG.64 =
// 4 halves per row), batch k = tid>>7; single 8-deep load batch per CTA.
// Last CTA (ticket) reduces the replicas, writes the scalar, and re-zeroes
// all accumulators for the next replay.
#define B_ROWS 8
__global__ void __launch_bounds__(512) k_main(const float* __restrict__ pm,
                                              float* __restrict__ out) {
    const float maxd = __int_as_float(g_maxbits);
    const float pmin = g_pmin;
    const float invr = 1.0f / (g_pmax - pmin);
    const float c0   = maxd + EPSF;

    const int tid = threadIdx.x;
    const int k   = tid >> 7;                 // batch (warp-uniform)
    const int n0  = blockIdx.x * B_ROWS;      // 1024 CTAs

    float4 acc = make_float4(0.f, 0.f, 0.f, 0.f);
    const float* pmk = pm + k * N_POSN;

    uint2 d[8];
    float pv[8];
    #pragma unroll
    for (int i = 0; i < 8; i++)
        d[i] = *reinterpret_cast<const uint2*>(g_Dg16 + (long long)(n0 + i) * NJ + 4 * tid);
    #pragma unroll
    for (int i = 0; i < 8; i++)
        pv[i] = __ldg(pmk + n0 + i);
    #pragma unroll
    for (int i = 0; i < 8; i++) {
        float p    = fminf(fmaxf((pv[i] - pmin) * invr, 0.0f), 1.0f);
        float base = fmaf(-p, maxd, c0);                   // (1-p)*maxd + eps
        float2 f0  = __half22float2(*reinterpret_cast<const __half2*>(&d[i].x));
        float2 f1  = __half22float2(*reinterpret_cast<const __half2*>(&d[i].y));
        acc.x += __fdividef(1.0f, fmaf(p, f0.x, base));
        acc.y += __fdividef(1.0f, fmaf(p, f0.y, base));
        acc.z += __fdividef(1.0f, fmaf(p, f1.x, base));
        acc.w += __fdividef(1.0f, fmaf(p, f1.y, base));
    }

    float* Srep = g_S[blockIdx.x & (NREP - 1)];
    atomicAdd(&Srep[4 * tid + 0], acc.x);
    atomicAdd(&Srep[4 * tid + 1], acc.y);
    atomicAdd(&Srep[4 * tid + 2], acc.z);
    atomicAdd(&Srep[4 * tid + 3], acc.w);

    // term1: threads 0..31 each handle one (b, row) pair; 8-lane segment reduce.
    if (tid < 32) {
        const int b = tid >> 3;
        const int n = n0 + (tid & 7);
        float pmv = __ldg(pm + b * N_POSN + n);
        float p   = fminf(fmaxf((pmv - pmin) * invr, 0.0f), 1.0f);
        float rm  = g_rowmin[b * N_POSN + n];
        float t1  = p * rm;
        float ne  = p;
        #pragma unroll
        for (int o = 4; o; o >>= 1) {
            t1 += __shfl_xor_sync(0xFFFFFFFFu, t1, o);
            ne += __shfl_xor_sync(0xFFFFFFFFu, ne, o);
        }
        if ((tid & 7) == 0) {
            atomicAdd(&g_t1[b], t1);
            atomicAdd(&g_ne[b], ne);
        }
    }

    // ---- fused finalize: last CTA to arrive reduces and resets ----
    __threadfence();
    __shared__ unsigned sticket;
    __shared__ float ssum[512];
    if (tid == 0) sticket = atomicAdd(&g_done, 1u);
    __syncthreads();
    if (sticket != (unsigned)(gridDim.x - 1)) return;

    // all other CTAs' atomics are visible (fence + L2-coherent __ldcg reads)
    float s = 0.0f;
    #pragma unroll
    for (int m = 0; m < NJ / 512; m++) {
        int j = tid + m * 512;
        float S = 0.0f;
        #pragma unroll
        for (int rp = 0; rp < NREP; rp++) S += __ldcg(&g_S[rp][j]);
        s += (float)N_POSN / S;
    }
    ssum[tid] = s;
    __syncthreads();
    for (int o = 256; o; o >>= 1) {
        if (tid < o) ssum[tid] += ssum[tid + o];
        __syncthreads();
    }
    if (tid == 0) {
        float term2 = ssum[0] / (float)(NB * NG);
        float term1 = 0.0f;
        #pragma unroll
        for (int b = 0; b < NB; b++)
            term1 += __ldcg(&g_t1[b]) / (__ldcg(&g_ne[b]) + EPSF);
        term1 *= (1.0f / NB);
        out[0] = term1 + term2;
    }
    __syncthreads();   // everyone done reading g_S / g_t1 / g_ne

    // reset accumulators for the next graph replay (matches module-load state)
    float* s0 = &g_S[0][0];
    for (int i = tid; i < NREP * NJ; i += 512) s0[i] = 0.0f;
    if (tid < NB) { g_t1[tid] = 0.0f; g_ne[tid] = 0.0f; }
    if (tid == 0) { g_maxbits = 0; g_done = 0u; }
}

// ---------------- launch ----------------
extern "C" void kernel_launch(void* const* d_in, const int* in_sizes, int n_in,
                              void* d_out, int out_size) {
    (void)in_sizes; (void)n_in; (void)out_size;
    const float* prob_map = (const float*)d_in[0];   // (4, 8192) f32
    const int*   gt       = (const int*)d_in[1];     // (4, 512)  i32
    const float* dis      = (const float*)d_in[2];   // (8192, 8192) f32
    float* out = (float*)d_out;

    k_gather<<<1024, 256>>>(dis, gt, prob_map);
    k_main<<<N_POSN / B_ROWS, 512>>>(prob_map, out);
}